// round 10
// baseline (speedup 1.0000x reference)
#include <cuda_runtime.h>
#include <cuda_bf16.h>
#include <cstdint>
#include <math.h>

// Problem constants
#define BB 32
#define NT 577
#define HH 12
#define DD 64
#define CC 768
#define MM (BB * NT)        // 18464
#define QKV_N (3 * CC)      // 2304

// ---------------------------------------------------------------------------
// Scratch (static device arrays: allocation-free per harness rules)
// ---------------------------------------------------------------------------
__device__ __nv_bfloat16 g_qh[(size_t)BB * HH * NT * DD];  // [B,H,N,D], scaled
__device__ __nv_bfloat16 g_ql[(size_t)BB * HH * NT * DD];
__device__ __nv_bfloat16 g_kh[(size_t)BB * HH * NT * DD];
__device__ __nv_bfloat16 g_kl[(size_t)BB * HH * NT * DD];
__device__ __nv_bfloat16 g_vh[(size_t)BB * HH * NT * DD];
__device__ __nv_bfloat16 g_vl[(size_t)BB * HH * NT * DD];

__device__ __nv_bfloat16 g_xhi[(size_t)MM * CC];
__device__ __nv_bfloat16 g_xlo[(size_t)MM * CC];
__device__ __nv_bfloat16 g_ohi[(size_t)MM * CC];   // attention out, [B,N,H*D]
__device__ __nv_bfloat16 g_olo[(size_t)MM * CC];
__device__ __nv_bfloat16 g_wqh[(size_t)QKV_N * CC];
__device__ __nv_bfloat16 g_wql[(size_t)QKV_N * CC];
__device__ __nv_bfloat16 g_wph[(size_t)CC * CC];
__device__ __nv_bfloat16 g_wpl[(size_t)CC * CC];

// ---------------------------------------------------------------------------
// Base-sm_100-safe PTX helpers (NO 'a'-gated instructions)
// ---------------------------------------------------------------------------
__device__ __forceinline__ uint32_t smem_u32(const void* p) {
    uint32_t a;
    asm("{ .reg .u64 t; cvta.to.shared.u64 t, %1; cvt.u32.u64 %0, t; }"
        : "=r"(a) : "l"(p));
    return a;
}

#define CP_ASYNC16(dst, src, sz) \
    asm volatile("cp.async.cg.shared.global [%0], [%1], 16, %2;" \
                 :: "r"(dst), "l"(src), "r"(sz))
#define CP_COMMIT() asm volatile("cp.async.commit_group;" ::: "memory")
#define CP_WAIT1()  asm volatile("cp.async.wait_group 1;" ::: "memory")
#define CP_WAIT0()  asm volatile("cp.async.wait_group 0;" ::: "memory")

__device__ __forceinline__ void ldsm_x4(uint32_t (&r)[4], uint32_t addr) {
    asm volatile("ldmatrix.sync.aligned.m8n8.x4.shared.b16 {%0,%1,%2,%3}, [%4];"
                 : "=r"(r[0]), "=r"(r[1]), "=r"(r[2]), "=r"(r[3]) : "r"(addr));
}

__device__ __forceinline__ void ldsm_x4_t(uint32_t (&r)[4], uint32_t addr) {
    asm volatile("ldmatrix.sync.aligned.m8n8.x4.trans.shared.b16 {%0,%1,%2,%3}, [%4];"
                 : "=r"(r[0]), "=r"(r[1]), "=r"(r[2]), "=r"(r[3]) : "r"(addr));
}

__device__ __forceinline__ void mma_bf16(float (&d)[4], const uint32_t (&a)[4],
                                         uint32_t b0, uint32_t b1) {
    asm volatile(
        "mma.sync.aligned.m16n8k16.row.col.f32.bf16.bf16.f32 "
        "{%0,%1,%2,%3}, {%4,%5,%6,%7}, {%8,%9}, {%0,%1,%2,%3};"
        : "+f"(d[0]), "+f"(d[1]), "+f"(d[2]), "+f"(d[3])
        : "r"(a[0]), "r"(a[1]), "r"(a[2]), "r"(a[3]), "r"(b0), "r"(b1));
}

__device__ __forceinline__ void split2(float a, float b,
                                       uint32_t& hi, uint32_t& lo) {
    __nv_bfloat162 h, l;
    h.x = __float2bfloat16(a); h.y = __float2bfloat16(b);
    l.x = __float2bfloat16(a - __bfloat162float(h.x));
    l.y = __float2bfloat16(b - __bfloat162float(h.y));
    hi = *(uint32_t*)&h; lo = *(uint32_t*)&l;
}

// ---------------------------------------------------------------------------
// fp32 -> bf16 hi/lo split of inputs/weights
// ---------------------------------------------------------------------------
__global__ __launch_bounds__(256)
void split_kernel(const float* __restrict__ x, const float* __restrict__ wq,
                  const float* __restrict__ wp)
{
    const int n0 = MM * CC / 4, n1 = QKV_N * CC / 4, n2 = CC * CC / 4;
    int i = blockIdx.x * blockDim.x + threadIdx.x;
    if (i >= n0 + n1 + n2) return;
    const float* src; __nv_bfloat16 *hp, *lp; int j;
    if (i < n0)           { src = x;  hp = g_xhi; lp = g_xlo; j = i; }
    else if (i < n0 + n1) { src = wq; hp = g_wqh; lp = g_wql; j = i - n0; }
    else                  { src = wp; hp = g_wph; lp = g_wpl; j = i - n0 - n1; }
    float4 v = ((const float4*)src)[j];
    uint32_t h0, l0, h1, l1;
    split2(v.x, v.y, h0, l0);
    split2(v.z, v.w, h1, l1);
    ((uint32_t*)(hp + 4 * (size_t)j))[0] = h0;
    ((uint32_t*)(hp + 4 * (size_t)j))[1] = h1;
    ((uint32_t*)(lp + 4 * (size_t)j))[0] = l0;
    ((uint32_t*)(lp + 4 * (size_t)j))[1] = l1;
}

// ---------------------------------------------------------------------------
// mma.sync GEMM, CTA tile 128x256, 8 warps (2x4), warp tile 64x64, BK=32.
// 2-term bf16 split: 3 MMAs per fragment pair (ah*bh + ah*bl + al*bh).
// Loader FIXED vs R8: 3072 chunks/stage (A: 2x512, B: 2x1024), 12 per thread.
// MODE 0: A=x(hi/lo), B=qkv_w(hi/lo); epilogue bias+RoPE+scale -> q/k/v hi/lo.
// MODE 1: A=o(hi/lo),  B=proj_w(hi/lo); epilogue +proj_b -> out.
// ---------------------------------------------------------------------------
#define LDK 40                        // padded row stride in bf16 (80 B)
#define A_BYTES (128 * LDK * 2)       // 10240 B per A array
#define B_BYTES (256 * LDK * 2)       // 20480 B per B array
#define STAGE_BYTES (2 * A_BYTES + 2 * B_BYTES)   // 61440
#define GEMM_DSMEM (2 * STAGE_BYTES)  // 122880 B
#define NKIT (CC / 32)                // 24 K-chunks

template <int MODE>
__global__ __launch_bounds__(256, 1)
void mma_gemm(const float* __restrict__ b0v, const float* __restrict__ b1v,
              const float* __restrict__ rope, float* __restrict__ Cout)
{
    extern __shared__ char dyn[];
    const uint32_t smem_base = smem_u32(dyn);

    const int tid = threadIdx.x;
    const int lane = tid & 31;
    const int wid = tid >> 5;
    const int wm = wid & 1;            // 2 warp-rows of 64
    const int wn = wid >> 1;           // 4 warp-cols of 64
    const int rowBase = blockIdx.y * 128;
    const int colBase = blockIdx.x * 256;

    const __nv_bfloat16* Ah = (MODE == 0) ? g_xhi : g_ohi;
    const __nv_bfloat16* Al = (MODE == 0) ? g_xlo : g_olo;
    const __nv_bfloat16* Bh = (MODE == 0) ? g_wqh : g_wph;
    const __nv_bfloat16* Bl = (MODE == 0) ? g_wql : g_wpl;

    // ---- stage loader: 3072 x 16B cp.async per stage, 12 per thread ----
    // A arrays: 128 rows x 4 chunks = 512 each (c in [0,1024))
    // B arrays: 256 rows x 4 chunks = 1024 each (c in [1024,3072))
    auto load_stage = [&](int stage, int k0) {
        const uint32_t sb = smem_base + stage * STAGE_BYTES;
#pragma unroll
        for (int t = 0; t < 12; ++t) {
            int c = t * 256 + tid;                 // 0..3071
            uint32_t dst;
            const __nv_bfloat16* src;
            int sz = 16;
            if (c < 1024) {                        // A: hi then lo, 128 rows
                int arr = c >> 9;                  // 0=Ah, 1=Al
                int rid = c & 511;
                int row = rid >> 2, kc = rid & 3;  // row 0..127
                dst = sb + arr * A_BYTES + row * (LDK * 2) + kc * 16;
                int m = rowBase + row;
                const __nv_bfloat16* p = arr ? Al : Ah;
                if (m < MM) src = p + (size_t)m * CC + k0 + kc * 8;
                else { src = p; sz = 0; }          // zero-fill pad rows
            } else {                               // B: hi then lo, 256 rows
                int c2 = c - 1024;
                int arr = c2 >> 10;                // 0=Bh, 1=Bl
                int rid = c2 & 1023;
                int row = rid >> 2, kc = rid & 3;  // row 0..255
                dst = sb + 2 * A_BYTES + arr * B_BYTES + row * (LDK * 2) + kc * 16;
                const __nv_bfloat16* p = arr ? Bl : Bh;
                src = p + (size_t)(colBase + row) * CC + k0 + kc * 8;
            }
            CP_ASYNC16(dst, src, sz);
        }
    };

    float acc[4][8][4];
#pragma unroll
    for (int mf = 0; mf < 4; ++mf)
#pragma unroll
        for (int nf = 0; nf < 8; ++nf)
#pragma unroll
            for (int r = 0; r < 4; ++r) acc[mf][nf][r] = 0.0f;

    const uint32_t lrow = lane & 15;
    const uint32_t lhalf = (lane >> 4) * 8;

    load_stage(0, 0);
    CP_COMMIT();

    for (int c = 0; c < NKIT; ++c) {
        if (c + 1 < NKIT) {
            load_stage((c + 1) & 1, (c + 1) * 32);
            CP_COMMIT();
            CP_WAIT1();
        } else {
            CP_WAIT0();
        }
        __syncthreads();

        const uint32_t sb = smem_base + (c & 1) * STAGE_BYTES;
#pragma unroll
        for (int kk = 0; kk < 32; kk += 16) {
            uint32_t a_h[4][4], a_l[4][4];
#pragma unroll
            for (int mf = 0; mf < 4; ++mf) {
                uint32_t off = ((wm * 64 + mf * 16 + lrow) * LDK + kk + lhalf) * 2;
                ldsm_x4(a_h[mf], sb + off);
                ldsm_x4(a_l[mf], sb + A_BYTES + off);
            }
            uint32_t bh[8][2], bl[8][2];
#pragma unroll
            for (int g = 0; g < 4; ++g) {
                uint32_t off = ((wn * 64 + g * 16 + lrow) * LDK + kk + lhalf) * 2;
                uint32_t r[4];
                ldsm_x4(r, sb + 2 * A_BYTES + off);
                bh[g * 2][0] = r[0]; bh[g * 2][1] = r[2];
                bh[g * 2 + 1][0] = r[1]; bh[g * 2 + 1][1] = r[3];
                ldsm_x4(r, sb + 2 * A_BYTES + B_BYTES + off);
                bl[g * 2][0] = r[0]; bl[g * 2][1] = r[2];
                bl[g * 2 + 1][0] = r[1]; bl[g * 2 + 1][1] = r[3];
            }
#pragma unroll
            for (int mf = 0; mf < 4; ++mf)
#pragma unroll
                for (int nf = 0; nf < 8; ++nf) {
                    mma_bf16(acc[mf][nf], a_h[mf], bh[nf][0], bh[nf][1]);
                    mma_bf16(acc[mf][nf], a_h[mf], bl[nf][0], bl[nf][1]);
                    mma_bf16(acc[mf][nf], a_l[mf], bh[nf][0], bh[nf][1]);
                }
        }
        __syncthreads();
    }

    // ---- epilogue ----
    const int r0 = lane >> 2;
    const int c0 = (lane & 3) * 2;
    const int cb = colBase + wn * 64 + c0;

    if (MODE == 0) {
        const int which = colBase / CC;            // uniform per block (256|768)
        __nv_bfloat16* dsth = (which == 0) ? g_qh : (which == 1) ? g_kh : g_vh;
        __nv_bfloat16* dstl = (which == 0) ? g_ql : (which == 1) ? g_kl : g_vl;
#pragma unroll
        for (int mf = 0; mf < 4; ++mf) {
#pragma unroll
            for (int half = 0; half < 2; ++half) {
                int m = rowBase + wm * 64 + mf * 16 + r0 + half * 8;
                if (m >= MM) continue;
                int bbr = m / NT;
                int tt = m - bbr * NT;
                const float* rp = rope + (size_t)(tt - 1) * (2 * DD);
#pragma unroll
                for (int nf = 0; nf < 8; ++nf) {
                    int rel = cb + nf * 8 - which * CC;
                    int h = rel >> 6;
                    int d0i = rel & 63;
                    float v0 = acc[mf][nf][half * 2 + 0];
                    float v1 = acc[mf][nf][half * 2 + 1];
                    if (which == 0) { v0 += b0v[rel]; v1 += b0v[rel + 1]; }
                    else if (which == 2) { v0 += b1v[rel]; v1 += b1v[rel + 1]; }
                    if (which < 2 && tt > 0) {
                        float sn0 = rp[d0i], sn1 = rp[d0i + 1];
                        float cs0 = rp[DD + d0i], cs1 = rp[DD + d0i + 1];
                        float xe = v0, xo = v1;
                        v0 = xe * cs0 - xo * sn0;
                        v1 = xo * cs1 + xe * sn1;
                    }
                    if (which == 0) { v0 *= 0.125f; v1 *= 0.125f; }
                    size_t idx = (((size_t)bbr * HH + h) * NT + tt) * DD + d0i;
                    uint32_t hi, lo;
                    split2(v0, v1, hi, lo);
                    *(uint32_t*)(dsth + idx) = hi;
                    *(uint32_t*)(dstl + idx) = lo;
                }
            }
        }
    } else {
#pragma unroll
        for (int mf = 0; mf < 4; ++mf) {
#pragma unroll
            for (int half = 0; half < 2; ++half) {
                int m = rowBase + wm * 64 + mf * 16 + r0 + half * 8;
                if (m >= MM) continue;
#pragma unroll
                for (int nf = 0; nf < 8; ++nf) {
                    int col = cb + nf * 8;
                    float v0 = acc[mf][nf][half * 2 + 0] + b0v[col];
                    float v1 = acc[mf][nf][half * 2 + 1] + b0v[col + 1];
                    *(float2*)(Cout + (size_t)m * CC + col) = make_float2(v0, v1);
                }
            }
        }
    }
}

// ---------------------------------------------------------------------------
// Fast exp on the FMA pipe
// ---------------------------------------------------------------------------
__device__ __forceinline__ float fexp(float x) {
    x = fmaxf(x, -80.0f);
    float y = x * 1.4426950408889634f;
    float n = rintf(y);
    float f = y - n;
    float p = 1.5402356e-4f;
    p = fmaf(p, f, 1.3333558e-3f);
    p = fmaf(p, f, 9.6181291e-3f);
    p = fmaf(p, f, 5.5504109e-2f);
    p = fmaf(p, f, 2.4022651e-1f);
    p = fmaf(p, f, 6.9314718e-1f);
    p = fmaf(p, f, 1.0f);
    return p * __int_as_float(((int)n + 127) << 23);
}

// ---------------------------------------------------------------------------
// Tensor-core flash attention: 64 q-rows/CTA, 128 threads (4 warps x m16),
// bf16-split S and PV MMAs, register softmax, cp.async double-buffered K/V.
// (Unchanged from the validated R7 kernel.)
// ---------------------------------------------------------------------------
#define LDV 72                          // padded row (144 B): conflict-free
#define FL_ARR 9216                     // 64*72*2 bytes per array
#define FL_KV 18432                     // after Qh, Ql
#define FL_STG 36864                    // Kh,Kl,Vh,Vl per stage
#define FL_SMEM (FL_KV + 2 * FL_STG)    // 92160 B

__global__ __launch_bounds__(128)
void flash_mma()
{
    extern __shared__ char fsm[];
    const uint32_t sb = smem_u32(fsm);
    const int tid = threadIdx.x;
    const int lane = tid & 31;
    const int wid = tid >> 5;
    const int bh = blockIdx.y;
    const int b = bh / HH;
    const int h = bh - b * HH;
    const int qbase = blockIdx.x * 64;
    const size_t head = ((size_t)b * HH + h) * NT * DD;

    // Q hi/lo tile: 1024 x 16B chunks
#pragma unroll
    for (int t = 0; t < 8; ++t) {
        int c = t * 128 + tid;
        int arr = c >> 9, rid = c & 511;
        int row = rid >> 3, kc = rid & 7;
        const __nv_bfloat16* src =
            (arr ? g_ql : g_qh) + head + (size_t)(qbase + row) * DD + kc * 8;
        int sz = (qbase + row < NT) ? 16 : 0;
        CP_ASYNC16(sb + arr * FL_ARR + row * 144 + kc * 16, src, sz);
    }

    auto load_kv = [&](int t, int s) {
        const int kvb = t * 64;
        const uint32_t base = sb + FL_KV + s * FL_STG;
#pragma unroll
        for (int u = 0; u < 16; ++u) {
            int c = u * 128 + tid;
            int arr = c >> 9, rid = c & 511;
            int row = rid >> 3, kc = rid & 7;
            const __nv_bfloat16* sp =
                (arr == 0) ? g_kh : (arr == 1) ? g_kl : (arr == 2) ? g_vh : g_vl;
            const __nv_bfloat16* src = sp + head + (size_t)(kvb + row) * DD + kc * 8;
            int sz = (kvb + row < NT) ? 16 : 0;
            CP_ASYNC16(base + arr * FL_ARR + row * 144 + kc * 16, src, sz);
        }
    };

    load_kv(0, 0);
    CP_COMMIT();

    float oacc[8][4];
#pragma unroll
    for (int nf = 0; nf < 8; ++nf)
#pragma unroll
        for (int r = 0; r < 4; ++r) oacc[nf][r] = 0.0f;
    float m0 = -1e30f, m1 = -1e30f, l0 = 0.0f, l1 = 0.0f;

    const uint32_t lrow = lane & 15;
    const uint32_t lhalf = (lane >> 4) * 8;
    const uint32_t vrow = (lane & 7) + 8 * ((lane >> 3) & 1);
    const uint32_t vcol = 8 * (lane >> 4);

    for (int t = 0; t < 10; ++t) {
        if (t + 1 < 10) { load_kv(t + 1, (t + 1) & 1); CP_COMMIT(); CP_WAIT1(); }
        else            { CP_WAIT0(); }
        __syncthreads();
        const uint32_t kb = sb + FL_KV + (t & 1) * FL_STG;

        // ---- S = Q K^T (bf16 split, fp32 accum) ----
        float sacc[8][4];
#pragma unroll
        for (int nf = 0; nf < 8; ++nf)
#pragma unroll
            for (int r = 0; r < 4; ++r) sacc[nf][r] = 0.0f;
#pragma unroll
        for (int kf = 0; kf < 4; ++kf) {
            uint32_t offa = ((wid * 16 + lrow) * LDV + kf * 16 + lhalf) * 2;
            uint32_t aqh[4], aql[4];
            ldsm_x4(aqh, sb + offa);
            ldsm_x4(aql, sb + FL_ARR + offa);
#pragma unroll
            for (int ng = 0; ng < 4; ++ng) {
                uint32_t offb = ((ng * 16 + lrow) * LDV + kf * 16 + lhalf) * 2;
                uint32_t rk[4], rl[4];
                ldsm_x4(rk, kb + offb);
                ldsm_x4(rl, kb + FL_ARR + offb);
                mma_bf16(sacc[2 * ng],     aqh, rk[0], rk[2]);
                mma_bf16(sacc[2 * ng + 1], aqh, rk[1], rk[3]);
                mma_bf16(sacc[2 * ng],     aqh, rl[0], rl[2]);
                mma_bf16(sacc[2 * ng + 1], aqh, rl[1], rl[3]);
                mma_bf16(sacc[2 * ng],     aql, rk[0], rk[2]);
                mma_bf16(sacc[2 * ng + 1], aql, rk[1], rk[3]);
            }
        }

        // ---- mask invalid kv columns (last tile only) ----
        const int kvb = t * 64;
        if (kvb + 64 > NT) {
#pragma unroll
            for (int nf = 0; nf < 8; ++nf) {
                int col = kvb + nf * 8 + (lane & 3) * 2;
                if (col >= NT)     { sacc[nf][0] = -1e30f; sacc[nf][2] = -1e30f; }
                if (col + 1 >= NT) { sacc[nf][1] = -1e30f; sacc[nf][3] = -1e30f; }
            }
        }

        // ---- online softmax (rows live in lane quads) ----
        float mx0 = -1e30f, mx1 = -1e30f;
#pragma unroll
        for (int nf = 0; nf < 8; ++nf) {
            mx0 = fmaxf(mx0, fmaxf(sacc[nf][0], sacc[nf][1]));
            mx1 = fmaxf(mx1, fmaxf(sacc[nf][2], sacc[nf][3]));
        }
        mx0 = fmaxf(mx0, __shfl_xor_sync(0xffffffffu, mx0, 1));
        mx0 = fmaxf(mx0, __shfl_xor_sync(0xffffffffu, mx0, 2));
        mx1 = fmaxf(mx1, __shfl_xor_sync(0xffffffffu, mx1, 1));
        mx1 = fmaxf(mx1, __shfl_xor_sync(0xffffffffu, mx1, 2));
        float mn0 = fmaxf(m0, mx0), mn1 = fmaxf(m1, mx1);
        float scl0 = fexp(m0 - mn0), scl1 = fexp(m1 - mn1);
        m0 = mn0; m1 = mn1;

        float rs0 = 0.0f, rs1 = 0.0f;
        uint32_t uph[8][2], upl[8][2];
#pragma unroll
        for (int nf = 0; nf < 8; ++nf) {
            float p0 = fexp(sacc[nf][0] - mn0);
            float p1 = fexp(sacc[nf][1] - mn0);
            float p2 = fexp(sacc[nf][2] - mn1);
            float p3 = fexp(sacc[nf][3] - mn1);
            rs0 += p0 + p1; rs1 += p2 + p3;
            split2(p0, p1, uph[nf][0], upl[nf][0]);
            split2(p2, p3, uph[nf][1], upl[nf][1]);
        }
        rs0 += __shfl_xor_sync(0xffffffffu, rs0, 1);
        rs0 += __shfl_xor_sync(0xffffffffu, rs0, 2);
        rs1 += __shfl_xor_sync(0xffffffffu, rs1, 1);
        rs1 += __shfl_xor_sync(0xffffffffu, rs1, 2);
        l0 = l0 * scl0 + rs0;
        l1 = l1 * scl1 + rs1;
#pragma unroll
        for (int nf = 0; nf < 8; ++nf) {
            oacc[nf][0] *= scl0; oacc[nf][1] *= scl0;
            oacc[nf][2] *= scl1; oacc[nf][3] *= scl1;
        }

        // ---- O += P V (bf16 split; V B-frags via ldmatrix.trans) ----
#pragma unroll
        for (int kf = 0; kf < 4; ++kf) {
            uint32_t ah[4] = {uph[2 * kf][0], uph[2 * kf][1],
                              uph[2 * kf + 1][0], uph[2 * kf + 1][1]};
            uint32_t al[4] = {upl[2 * kf][0], upl[2 * kf][1],
                              upl[2 * kf + 1][0], upl[2 * kf + 1][1]};
#pragma unroll
            for (int g = 0; g < 4; ++g) {
                uint32_t offv = ((kf * 16 + vrow) * LDV + g * 16 + vcol) * 2;
                uint32_t vh[4], vl[4];
                ldsm_x4_t(vh, kb + 2 * FL_ARR + offv);
                ldsm_x4_t(vl, kb + 3 * FL_ARR + offv);
                mma_bf16(oacc[2 * g],     ah, vh[0], vh[1]);
                mma_bf16(oacc[2 * g + 1], ah, vh[2], vh[3]);
                mma_bf16(oacc[2 * g],     ah, vl[0], vl[1]);
                mma_bf16(oacc[2 * g + 1], ah, vl[2], vl[3]);
                mma_bf16(oacc[2 * g],     al, vh[0], vh[1]);
                mma_bf16(oacc[2 * g + 1], al, vh[2], vh[3]);
            }
        }
        __syncthreads();
    }

    // ---- normalize + bf16 hi/lo write to [B,N,H*D] ----
    const float inv0 = 1.0f / l0, inv1 = 1.0f / l1;
    const int qr0 = qbase + wid * 16 + (lane >> 2);
    const int d0 = (lane & 3) * 2;
    if (qr0 < NT) {
        size_t o = ((size_t)b * NT + qr0) * CC + h * DD;
#pragma unroll
        for (int nf = 0; nf < 8; ++nf) {
            uint32_t hi, lo;
            split2(oacc[nf][0] * inv0, oacc[nf][1] * inv0, hi, lo);
            *(uint32_t*)(g_ohi + o + nf * 8 + d0) = hi;
            *(uint32_t*)(g_olo + o + nf * 8 + d0) = lo;
        }
    }
    const int qr1 = qr0 + 8;
    if (qr1 < NT) {
        size_t o = ((size_t)b * NT + qr1) * CC + h * DD;
#pragma unroll
        for (int nf = 0; nf < 8; ++nf) {
            uint32_t hi, lo;
            split2(oacc[nf][2] * inv1, oacc[nf][3] * inv1, hi, lo);
            *(uint32_t*)(g_ohi + o + nf * 8 + d0) = hi;
            *(uint32_t*)(g_olo + o + nf * 8 + d0) = lo;
        }
    }
}

// ---------------------------------------------------------------------------

extern "C" void kernel_launch(void* const* d_in, const int* in_sizes, int n_in,
                              void* d_out, int out_size)
{
    const float* x      = (const float*)d_in[0];
    const float* rope   = (const float*)d_in[1];
    const float* qkv_w  = (const float*)d_in[2];
    const float* q_bias = (const float*)d_in[3];
    const float* v_bias = (const float*)d_in[4];
    const float* proj_w = (const float*)d_in[5];
    const float* proj_b = (const float*)d_in[6];
    float* out = (float*)d_out;
    (void)in_sizes; (void)n_in; (void)out_size;

    // 0) split fp32 inputs/weights into bf16 hi/lo
    const int total4 = (MM * CC + QKV_N * CC + CC * CC) / 4;
    split_kernel<<<(total4 + 255) / 256, 256>>>(x, qkv_w, proj_w);

    const int mtiles = (MM + 127) / 128;   // 145

    // 1) QKV GEMM (mma.sync) + bias + RoPE + q-scale -> q/k/v bf16 hi/lo
    cudaFuncSetAttribute(mma_gemm<0>,
                         cudaFuncAttributeMaxDynamicSharedMemorySize, GEMM_DSMEM);
    mma_gemm<0><<<dim3(QKV_N / 256, mtiles), 256, GEMM_DSMEM>>>(
        q_bias, v_bias, rope, nullptr);

    // 2) tensor-core flash attention -> g_ohi/g_olo
    cudaFuncSetAttribute(flash_mma,
                         cudaFuncAttributeMaxDynamicSharedMemorySize, FL_SMEM);
    flash_mma<<<dim3(10, BB * HH), 128, FL_SMEM>>>();

    // 3) output projection (mma.sync) -> out
    cudaFuncSetAttribute(mma_gemm<1>,
                         cudaFuncAttributeMaxDynamicSharedMemorySize, GEMM_DSMEM);
    mma_gemm<1><<<dim3(CC / 256, mtiles), 256, GEMM_DSMEM>>>(
        proj_b, nullptr, nullptr, out);
}

// round 11
// speedup vs baseline: 1.0848x; 1.0848x over previous
#include <cuda_runtime.h>
#include <cuda_bf16.h>
#include <cstdint>
#include <math.h>

// Problem constants
#define BB 32
#define NT 577
#define HH 12
#define DD 64
#define CC 768
#define MM (BB * NT)        // 18464
#define QKV_N (3 * CC)      // 2304

// ---------------------------------------------------------------------------
// Scratch (static device arrays: allocation-free per harness rules)
// ---------------------------------------------------------------------------
__device__ __nv_bfloat16 g_qh[(size_t)BB * HH * NT * DD];  // [B,H,N,D], scaled
__device__ __nv_bfloat16 g_ql[(size_t)BB * HH * NT * DD];
__device__ __nv_bfloat16 g_kh[(size_t)BB * HH * NT * DD];
__device__ __nv_bfloat16 g_kl[(size_t)BB * HH * NT * DD];
__device__ __nv_bfloat16 g_vh[(size_t)BB * HH * NT * DD];
__device__ __nv_bfloat16 g_vl[(size_t)BB * HH * NT * DD];

__device__ __nv_bfloat16 g_xhi[(size_t)MM * CC];
__device__ __nv_bfloat16 g_xlo[(size_t)MM * CC];
__device__ __nv_bfloat16 g_ohi[(size_t)MM * CC];   // attention out, [B,N,H*D]
__device__ __nv_bfloat16 g_olo[(size_t)MM * CC];
__device__ __nv_bfloat16 g_wqh[(size_t)QKV_N * CC];
__device__ __nv_bfloat16 g_wql[(size_t)QKV_N * CC];
__device__ __nv_bfloat16 g_wph[(size_t)CC * CC];
__device__ __nv_bfloat16 g_wpl[(size_t)CC * CC];

// ---------------------------------------------------------------------------
// Base-sm_100-safe PTX helpers (NO 'a'-gated instructions)
// ---------------------------------------------------------------------------
__device__ __forceinline__ uint32_t smem_u32(const void* p) {
    uint32_t a;
    asm("{ .reg .u64 t; cvta.to.shared.u64 t, %1; cvt.u32.u64 %0, t; }"
        : "=r"(a) : "l"(p));
    return a;
}

#define CP_ASYNC16(dst, src, sz) \
    asm volatile("cp.async.cg.shared.global [%0], [%1], 16, %2;" \
                 :: "r"(dst), "l"(src), "r"(sz))
#define CP_COMMIT() asm volatile("cp.async.commit_group;" ::: "memory")
#define CP_WAIT1()  asm volatile("cp.async.wait_group 1;" ::: "memory")
#define CP_WAIT0()  asm volatile("cp.async.wait_group 0;" ::: "memory")

__device__ __forceinline__ void ldsm_x4(uint32_t (&r)[4], uint32_t addr) {
    asm volatile("ldmatrix.sync.aligned.m8n8.x4.shared.b16 {%0,%1,%2,%3}, [%4];"
                 : "=r"(r[0]), "=r"(r[1]), "=r"(r[2]), "=r"(r[3]) : "r"(addr));
}

__device__ __forceinline__ void ldsm_x4_t(uint32_t (&r)[4], uint32_t addr) {
    asm volatile("ldmatrix.sync.aligned.m8n8.x4.trans.shared.b16 {%0,%1,%2,%3}, [%4];"
                 : "=r"(r[0]), "=r"(r[1]), "=r"(r[2]), "=r"(r[3]) : "r"(addr));
}

__device__ __forceinline__ void mma_bf16(float (&d)[4], const uint32_t (&a)[4],
                                         uint32_t b0, uint32_t b1) {
    asm volatile(
        "mma.sync.aligned.m16n8k16.row.col.f32.bf16.bf16.f32 "
        "{%0,%1,%2,%3}, {%4,%5,%6,%7}, {%8,%9}, {%0,%1,%2,%3};"
        : "+f"(d[0]), "+f"(d[1]), "+f"(d[2]), "+f"(d[3])
        : "r"(a[0]), "r"(a[1]), "r"(a[2]), "r"(a[3]), "r"(b0), "r"(b1));
}

__device__ __forceinline__ void split2(float a, float b,
                                       uint32_t& hi, uint32_t& lo) {
    __nv_bfloat162 h, l;
    h.x = __float2bfloat16(a); h.y = __float2bfloat16(b);
    l.x = __float2bfloat16(a - __bfloat162float(h.x));
    l.y = __float2bfloat16(b - __bfloat162float(h.y));
    hi = *(uint32_t*)&h; lo = *(uint32_t*)&l;
}

// ---------------------------------------------------------------------------
// fp32 -> bf16 hi/lo split of inputs/weights
// ---------------------------------------------------------------------------
__global__ __launch_bounds__(256)
void split_kernel(const float* __restrict__ x, const float* __restrict__ wq,
                  const float* __restrict__ wp)
{
    const int n0 = MM * CC / 4, n1 = QKV_N * CC / 4, n2 = CC * CC / 4;
    int i = blockIdx.x * blockDim.x + threadIdx.x;
    if (i >= n0 + n1 + n2) return;
    const float* src; __nv_bfloat16 *hp, *lp; int j;
    if (i < n0)           { src = x;  hp = g_xhi; lp = g_xlo; j = i; }
    else if (i < n0 + n1) { src = wq; hp = g_wqh; lp = g_wql; j = i - n0; }
    else                  { src = wp; hp = g_wph; lp = g_wpl; j = i - n0 - n1; }
    float4 v = ((const float4*)src)[j];
    uint32_t h0, l0, h1, l1;
    split2(v.x, v.y, h0, l0);
    split2(v.z, v.w, h1, l1);
    ((uint32_t*)(hp + 4 * (size_t)j))[0] = h0;
    ((uint32_t*)(hp + 4 * (size_t)j))[1] = h1;
    ((uint32_t*)(lp + 4 * (size_t)j))[0] = l0;
    ((uint32_t*)(lp + 4 * (size_t)j))[1] = l1;
}

// ---------------------------------------------------------------------------
// QKV GEMM — validated R7 config: CTA 128x128, 8 warps (2x4), warp 64x32,
// BK=32, 2 CTA/SM. Epilogue: bias + RoPE + q-scale -> q/k/v bf16 hi/lo.
// ---------------------------------------------------------------------------
#define LDKQ 40
#define QAB (128 * LDKQ * 2)            // 10240 B per array
#define QSTG (4 * QAB)                  // 40960 B per stage
#define QDSMEM (2 * QSTG)               // 81920 B
#define NKIT (CC / 32)                  // 24

__global__ __launch_bounds__(256)
void mma_gemm_qkv(const float* __restrict__ b0v, const float* __restrict__ b1v,
                  const float* __restrict__ rope)
{
    extern __shared__ char dyn[];
    const uint32_t smem_base = smem_u32(dyn);

    const int tid = threadIdx.x;
    const int lane = tid & 31;
    const int wid = tid >> 5;
    const int wm = wid & 1;
    const int wn = wid >> 1;
    const int rowBase = blockIdx.y * 128;
    const int colBase = blockIdx.x * 128;

    auto load_stage = [&](int stage, int k0) {
        const uint32_t sb = smem_base + stage * QSTG;
#pragma unroll
        for (int t = 0; t < 8; ++t) {
            int c = t * 256 + tid;
            int arr = c >> 9;              // 0=Ah 1=Al 2=Bh 3=Bl
            int rid = c & 511;
            int row = rid >> 2;
            int kc = rid & 3;
            uint32_t dst = sb + arr * QAB + row * (LDKQ * 2) + kc * 16;
            const __nv_bfloat16* src;
            int sz = 16;
            if (arr < 2) {
                int m = rowBase + row;
                const __nv_bfloat16* p = arr ? g_xlo : g_xhi;
                if (m < MM) src = p + (size_t)m * CC + k0 + kc * 8;
                else { src = p; sz = 0; }
            } else {
                const __nv_bfloat16* p = (arr == 2) ? g_wqh : g_wql;
                src = p + (size_t)(colBase + row) * CC + k0 + kc * 8;
            }
            CP_ASYNC16(dst, src, sz);
        }
    };

    float acc[4][4][4];
#pragma unroll
    for (int mf = 0; mf < 4; ++mf)
#pragma unroll
        for (int nf = 0; nf < 4; ++nf)
#pragma unroll
            for (int r = 0; r < 4; ++r) acc[mf][nf][r] = 0.0f;

    const uint32_t lrow = lane & 15;
    const uint32_t lhalf = (lane >> 4) * 8;

    load_stage(0, 0);
    CP_COMMIT();

    for (int c = 0; c < NKIT; ++c) {
        if (c + 1 < NKIT) {
            load_stage((c + 1) & 1, (c + 1) * 32);
            CP_COMMIT();
            CP_WAIT1();
        } else {
            CP_WAIT0();
        }
        __syncthreads();

        const uint32_t sb = smem_base + (c & 1) * QSTG;
#pragma unroll
        for (int kk = 0; kk < 32; kk += 16) {
            uint32_t a_h[4][4], a_l[4][4];
#pragma unroll
            for (int mf = 0; mf < 4; ++mf) {
                uint32_t off = ((wm * 64 + mf * 16 + lrow) * LDKQ + kk + lhalf) * 2;
                ldsm_x4(a_h[mf], sb + off);
                ldsm_x4(a_l[mf], sb + QAB + off);
            }
            uint32_t bh[4][2], bl[4][2];
#pragma unroll
            for (int g = 0; g < 2; ++g) {
                uint32_t off = ((wn * 32 + g * 16 + lrow) * LDKQ + kk + lhalf) * 2;
                uint32_t r[4];
                ldsm_x4(r, sb + 2 * QAB + off);
                bh[g * 2][0] = r[0]; bh[g * 2][1] = r[2];
                bh[g * 2 + 1][0] = r[1]; bh[g * 2 + 1][1] = r[3];
                ldsm_x4(r, sb + 3 * QAB + off);
                bl[g * 2][0] = r[0]; bl[g * 2][1] = r[2];
                bl[g * 2 + 1][0] = r[1]; bl[g * 2 + 1][1] = r[3];
            }
#pragma unroll
            for (int mf = 0; mf < 4; ++mf)
#pragma unroll
                for (int nf = 0; nf < 4; ++nf) {
                    mma_bf16(acc[mf][nf], a_h[mf], bh[nf][0], bh[nf][1]);
                    mma_bf16(acc[mf][nf], a_h[mf], bl[nf][0], bl[nf][1]);
                    mma_bf16(acc[mf][nf], a_l[mf], bh[nf][0], bh[nf][1]);
                }
        }
        __syncthreads();
    }

    const int r0 = lane >> 2;
    const int c0 = (lane & 3) * 2;
    const int cb = colBase + wn * 32 + c0;

    const int which = colBase / CC;
    __nv_bfloat16* dsth = (which == 0) ? g_qh : (which == 1) ? g_kh : g_vh;
    __nv_bfloat16* dstl = (which == 0) ? g_ql : (which == 1) ? g_kl : g_vl;
#pragma unroll
    for (int mf = 0; mf < 4; ++mf) {
#pragma unroll
        for (int half = 0; half < 2; ++half) {
            int m = rowBase + wm * 64 + mf * 16 + r0 + half * 8;
            if (m >= MM) continue;
            int bbr = m / NT;
            int tt = m - bbr * NT;
            const float* rp = rope + (size_t)(tt - 1) * (2 * DD);
#pragma unroll
            for (int nf = 0; nf < 4; ++nf) {
                int rel = cb + nf * 8 - which * CC;
                int h = rel >> 6;
                int d0i = rel & 63;
                float v0 = acc[mf][nf][half * 2 + 0];
                float v1 = acc[mf][nf][half * 2 + 1];
                if (which == 0) { v0 += b0v[rel]; v1 += b0v[rel + 1]; }
                else if (which == 2) { v0 += b1v[rel]; v1 += b1v[rel + 1]; }
                if (which < 2 && tt > 0) {
                    float sn0 = rp[d0i], sn1 = rp[d0i + 1];
                    float cs0 = rp[DD + d0i], cs1 = rp[DD + d0i + 1];
                    float xe = v0, xo = v1;
                    v0 = xe * cs0 - xo * sn0;
                    v1 = xo * cs1 + xe * sn1;
                }
                if (which == 0) { v0 *= 0.125f; v1 *= 0.125f; }
                size_t idx = (((size_t)bbr * HH + h) * NT + tt) * DD + d0i;
                uint32_t hi, lo;
                split2(v0, v1, hi, lo);
                *(uint32_t*)(dsth + idx) = hi;
                *(uint32_t*)(dstl + idx) = lo;
            }
        }
    }
}

// ---------------------------------------------------------------------------
// Projection GEMM — validated R10 config: CTA 128x256, warp 64x64, BK=32,
// 1 CTA/SM. Epilogue: +proj_b -> out (fp32).
// ---------------------------------------------------------------------------
#define LDKP 40
#define PA_BYTES (128 * LDKP * 2)       // 10240
#define PB_BYTES (256 * LDKP * 2)       // 20480
#define PSTG (2 * PA_BYTES + 2 * PB_BYTES)  // 61440
#define PDSMEM (2 * PSTG)               // 122880

__global__ __launch_bounds__(256, 1)
void mma_gemm_proj(const float* __restrict__ b0v, float* __restrict__ Cout)
{
    extern __shared__ char dyn[];
    const uint32_t smem_base = smem_u32(dyn);

    const int tid = threadIdx.x;
    const int lane = tid & 31;
    const int wid = tid >> 5;
    const int wm = wid & 1;
    const int wn = wid >> 1;
    const int rowBase = blockIdx.y * 128;
    const int colBase = blockIdx.x * 256;

    auto load_stage = [&](int stage, int k0) {
        const uint32_t sb = smem_base + stage * PSTG;
#pragma unroll
        for (int t = 0; t < 12; ++t) {
            int c = t * 256 + tid;                 // 0..3071
            uint32_t dst;
            const __nv_bfloat16* src;
            int sz = 16;
            if (c < 1024) {                        // A: hi then lo, 128 rows
                int arr = c >> 9;
                int rid = c & 511;
                int row = rid >> 2, kc = rid & 3;
                dst = sb + arr * PA_BYTES + row * (LDKP * 2) + kc * 16;
                int m = rowBase + row;
                const __nv_bfloat16* p = arr ? g_olo : g_ohi;
                if (m < MM) src = p + (size_t)m * CC + k0 + kc * 8;
                else { src = p; sz = 0; }
            } else {                               // B: hi then lo, 256 rows
                int c2 = c - 1024;
                int arr = c2 >> 10;
                int rid = c2 & 1023;
                int row = rid >> 2, kc = rid & 3;
                dst = sb + 2 * PA_BYTES + arr * PB_BYTES + row * (LDKP * 2) + kc * 16;
                const __nv_bfloat16* p = arr ? g_wpl : g_wph;
                src = p + (size_t)(colBase + row) * CC + k0 + kc * 8;
            }
            CP_ASYNC16(dst, src, sz);
        }
    };

    float acc[4][8][4];
#pragma unroll
    for (int mf = 0; mf < 4; ++mf)
#pragma unroll
        for (int nf = 0; nf < 8; ++nf)
#pragma unroll
            for (int r = 0; r < 4; ++r) acc[mf][nf][r] = 0.0f;

    const uint32_t lrow = lane & 15;
    const uint32_t lhalf = (lane >> 4) * 8;

    load_stage(0, 0);
    CP_COMMIT();

    for (int c = 0; c < NKIT; ++c) {
        if (c + 1 < NKIT) {
            load_stage((c + 1) & 1, (c + 1) * 32);
            CP_COMMIT();
            CP_WAIT1();
        } else {
            CP_WAIT0();
        }
        __syncthreads();

        const uint32_t sb = smem_base + (c & 1) * PSTG;
#pragma unroll
        for (int kk = 0; kk < 32; kk += 16) {
            uint32_t a_h[4][4], a_l[4][4];
#pragma unroll
            for (int mf = 0; mf < 4; ++mf) {
                uint32_t off = ((wm * 64 + mf * 16 + lrow) * LDKP + kk + lhalf) * 2;
                ldsm_x4(a_h[mf], sb + off);
                ldsm_x4(a_l[mf], sb + PA_BYTES + off);
            }
            uint32_t bh[8][2], bl[8][2];
#pragma unroll
            for (int g = 0; g < 4; ++g) {
                uint32_t off = ((wn * 64 + g * 16 + lrow) * LDKP + kk + lhalf) * 2;
                uint32_t r[4];
                ldsm_x4(r, sb + 2 * PA_BYTES + off);
                bh[g * 2][0] = r[0]; bh[g * 2][1] = r[2];
                bh[g * 2 + 1][0] = r[1]; bh[g * 2 + 1][1] = r[3];
                ldsm_x4(r, sb + 2 * PA_BYTES + PB_BYTES + off);
                bl[g * 2][0] = r[0]; bl[g * 2][1] = r[2];
                bl[g * 2 + 1][0] = r[1]; bl[g * 2 + 1][1] = r[3];
            }
#pragma unroll
            for (int mf = 0; mf < 4; ++mf)
#pragma unroll
                for (int nf = 0; nf < 8; ++nf) {
                    mma_bf16(acc[mf][nf], a_h[mf], bh[nf][0], bh[nf][1]);
                    mma_bf16(acc[mf][nf], a_h[mf], bl[nf][0], bl[nf][1]);
                    mma_bf16(acc[mf][nf], a_l[mf], bh[nf][0], bh[nf][1]);
                }
        }
        __syncthreads();
    }

    const int r0 = lane >> 2;
    const int c0 = (lane & 3) * 2;
    const int cb = colBase + wn * 64 + c0;
#pragma unroll
    for (int mf = 0; mf < 4; ++mf) {
#pragma unroll
        for (int half = 0; half < 2; ++half) {
            int m = rowBase + wm * 64 + mf * 16 + r0 + half * 8;
            if (m >= MM) continue;
#pragma unroll
            for (int nf = 0; nf < 8; ++nf) {
                int col = cb + nf * 8;
                float v0 = acc[mf][nf][half * 2 + 0] + b0v[col];
                float v1 = acc[mf][nf][half * 2 + 1] + b0v[col + 1];
                *(float2*)(Cout + (size_t)m * CC + col) = make_float2(v0, v1);
            }
        }
    }
}

// ---------------------------------------------------------------------------
// Fast exp on the FMA pipe
// ---------------------------------------------------------------------------
__device__ __forceinline__ float fexp(float x) {
    x = fmaxf(x, -80.0f);
    float y = x * 1.4426950408889634f;
    float n = rintf(y);
    float f = y - n;
    float p = 1.5402356e-4f;
    p = fmaf(p, f, 1.3333558e-3f);
    p = fmaf(p, f, 9.6181291e-3f);
    p = fmaf(p, f, 5.5504109e-2f);
    p = fmaf(p, f, 2.4022651e-1f);
    p = fmaf(p, f, 6.9314718e-1f);
    p = fmaf(p, f, 1.0f);
    return p * __int_as_float(((int)n + 127) << 23);
}

// ---------------------------------------------------------------------------
// Tensor-core flash attention (validated R7 core). NOW: 9 MMA iterations
// cover kv 0..575 (576 = 9*64 exactly); kv row 576 is folded in as one exact
// fp32 online-softmax step in registers (saves the 90%-padded 10th tile).
// ---------------------------------------------------------------------------
#define LDV 72                          // padded row (144 B): conflict-free
#define FL_ARR 9216                     // 64*72*2 bytes per array
#define FL_KV 18432                     // after Qh, Ql
#define FL_STG 36864                    // Kh,Kl,Vh,Vl per stage
#define FL_SMEM (FL_KV + 2 * FL_STG)    // 92160 B
#define NKV_IT 9                        // kv tiles 0..8 (576 rows)

__global__ __launch_bounds__(128)
void flash_mma()
{
    extern __shared__ char fsm[];
    const uint32_t sb = smem_u32(fsm);
    const int tid = threadIdx.x;
    const int lane = tid & 31;
    const int wid = tid >> 5;
    const int bh = blockIdx.y;
    const int b = bh / HH;
    const int h = bh - b * HH;
    const int qbase = blockIdx.x * 64;
    const size_t head = ((size_t)b * HH + h) * NT * DD;

    // Q hi/lo tile: 1024 x 16B chunks
#pragma unroll
    for (int t = 0; t < 8; ++t) {
        int c = t * 128 + tid;
        int arr = c >> 9, rid = c & 511;
        int row = rid >> 3, kc = rid & 7;
        const __nv_bfloat16* src =
            (arr ? g_ql : g_qh) + head + (size_t)(qbase + row) * DD + kc * 8;
        int sz = (qbase + row < NT) ? 16 : 0;
        CP_ASYNC16(sb + arr * FL_ARR + row * 144 + kc * 16, src, sz);
    }

    auto load_kv = [&](int t, int s) {
        const int kvb = t * 64;
        const uint32_t base = sb + FL_KV + s * FL_STG;
#pragma unroll
        for (int u = 0; u < 16; ++u) {
            int c = u * 128 + tid;
            int arr = c >> 9, rid = c & 511;
            int row = rid >> 3, kc = rid & 7;
            const __nv_bfloat16* sp =
                (arr == 0) ? g_kh : (arr == 1) ? g_kl : (arr == 2) ? g_vh : g_vl;
            const __nv_bfloat16* src = sp + head + (size_t)(kvb + row) * DD + kc * 8;
            CP_ASYNC16(base + arr * FL_ARR + row * 144 + kc * 16, src, 16);
        }
    };

    load_kv(0, 0);
    CP_COMMIT();

    float oacc[8][4];
#pragma unroll
    for (int nf = 0; nf < 8; ++nf)
#pragma unroll
        for (int r = 0; r < 4; ++r) oacc[nf][r] = 0.0f;
    float m0 = -1e30f, m1 = -1e30f, l0 = 0.0f, l1 = 0.0f;

    const uint32_t lrow = lane & 15;
    const uint32_t lhalf = (lane >> 4) * 8;
    const uint32_t vrow = (lane & 7) + 8 * ((lane >> 3) & 1);
    const uint32_t vcol = 8 * (lane >> 4);

    for (int t = 0; t < NKV_IT; ++t) {
        if (t + 1 < NKV_IT) { load_kv(t + 1, (t + 1) & 1); CP_COMMIT(); CP_WAIT1(); }
        else                { CP_WAIT0(); }
        __syncthreads();
        const uint32_t kb = sb + FL_KV + (t & 1) * FL_STG;

        // ---- S = Q K^T (bf16 split, fp32 accum) ----
        float sacc[8][4];
#pragma unroll
        for (int nf = 0; nf < 8; ++nf)
#pragma unroll
            for (int r = 0; r < 4; ++r) sacc[nf][r] = 0.0f;
#pragma unroll
        for (int kf = 0; kf < 4; ++kf) {
            uint32_t offa = ((wid * 16 + lrow) * LDV + kf * 16 + lhalf) * 2;
            uint32_t aqh[4], aql[4];
            ldsm_x4(aqh, sb + offa);
            ldsm_x4(aql, sb + FL_ARR + offa);
#pragma unroll
            for (int ng = 0; ng < 4; ++ng) {
                uint32_t offb = ((ng * 16 + lrow) * LDV + kf * 16 + lhalf) * 2;
                uint32_t rk[4], rl[4];
                ldsm_x4(rk, kb + offb);
                ldsm_x4(rl, kb + FL_ARR + offb);
                mma_bf16(sacc[2 * ng],     aqh, rk[0], rk[2]);
                mma_bf16(sacc[2 * ng + 1], aqh, rk[1], rk[3]);
                mma_bf16(sacc[2 * ng],     aqh, rl[0], rl[2]);
                mma_bf16(sacc[2 * ng + 1], aqh, rl[1], rl[3]);
                mma_bf16(sacc[2 * ng],     aql, rk[0], rk[2]);
                mma_bf16(sacc[2 * ng + 1], aql, rk[1], rk[3]);
            }
        }

        // ---- online softmax (rows live in lane quads); all 576 kv valid ----
        float mx0 = -1e30f, mx1 = -1e30f;
#pragma unroll
        for (int nf = 0; nf < 8; ++nf) {
            mx0 = fmaxf(mx0, fmaxf(sacc[nf][0], sacc[nf][1]));
            mx1 = fmaxf(mx1, fmaxf(sacc[nf][2], sacc[nf][3]));
        }
        mx0 = fmaxf(mx0, __shfl_xor_sync(0xffffffffu, mx0, 1));
        mx0 = fmaxf(mx0, __shfl_xor_sync(0xffffffffu, mx0, 2));
        mx1 = fmaxf(mx1, __shfl_xor_sync(0xffffffffu, mx1, 1));
        mx1 = fmaxf(mx1, __shfl_xor_sync(0xffffffffu, mx1, 2));
        float mn0 = fmaxf(m0, mx0), mn1 = fmaxf(m1, mx1);
        float scl0 = fexp(m0 - mn0), scl1 = fexp(m1 - mn1);
        m0 = mn0; m1 = mn1;

        float rs0 = 0.0f, rs1 = 0.0f;
        uint32_t uph[8][2], upl[8][2];
#pragma unroll
        for (int nf = 0; nf < 8; ++nf) {
            float p0 = fexp(sacc[nf][0] - mn0);
            float p1 = fexp(sacc[nf][1] - mn0);
            float p2 = fexp(sacc[nf][2] - mn1);
            float p3 = fexp(sacc[nf][3] - mn1);
            rs0 += p0 + p1; rs1 += p2 + p3;
            split2(p0, p1, uph[nf][0], upl[nf][0]);
            split2(p2, p3, uph[nf][1], upl[nf][1]);
        }
        rs0 += __shfl_xor_sync(0xffffffffu, rs0, 1);
        rs0 += __shfl_xor_sync(0xffffffffu, rs0, 2);
        rs1 += __shfl_xor_sync(0xffffffffu, rs1, 1);
        rs1 += __shfl_xor_sync(0xffffffffu, rs1, 2);
        l0 = l0 * scl0 + rs0;
        l1 = l1 * scl1 + rs1;
#pragma unroll
        for (int nf = 0; nf < 8; ++nf) {
            oacc[nf][0] *= scl0; oacc[nf][1] *= scl0;
            oacc[nf][2] *= scl1; oacc[nf][3] *= scl1;
        }

        // ---- O += P V (bf16 split; V B-frags via ldmatrix.trans) ----
#pragma unroll
        for (int kf = 0; kf < 4; ++kf) {
            uint32_t ah[4] = {uph[2 * kf][0], uph[2 * kf][1],
                              uph[2 * kf + 1][0], uph[2 * kf + 1][1]};
            uint32_t al[4] = {upl[2 * kf][0], upl[2 * kf][1],
                              upl[2 * kf + 1][0], upl[2 * kf + 1][1]};
#pragma unroll
            for (int g = 0; g < 4; ++g) {
                uint32_t offv = ((kf * 16 + vrow) * LDV + g * 16 + vcol) * 2;
                uint32_t vh[4], vl[4];
                ldsm_x4_t(vh, kb + 2 * FL_ARR + offv);
                ldsm_x4_t(vl, kb + 3 * FL_ARR + offv);
                mma_bf16(oacc[2 * g],     ah, vh[0], vh[1]);
                mma_bf16(oacc[2 * g + 1], ah, vh[2], vh[3]);
                mma_bf16(oacc[2 * g],     ah, vl[0], vl[1]);
                mma_bf16(oacc[2 * g + 1], ah, vl[2], vl[3]);
                mma_bf16(oacc[2 * g],     al, vh[0], vh[1]);
                mma_bf16(oacc[2 * g + 1], al, vh[2], vh[3]);
            }
        }
        __syncthreads();
    }

    // ---- exact fp32 tail: kv row 576 as one online-softmax step ----
    {
        const int d0 = (lane & 3) * 2;
        const int dstart = (lane & 3) * 16;          // quad-lane covers 16 d's
        const int r0l = wid * 16 + (lane >> 2);      // local q rows (smem)
        const int r1l = r0l + 8;
        const __nv_bfloat16* kh = g_kh + head + (size_t)576 * DD;
        const __nv_bfloat16* kl = g_kl + head + (size_t)576 * DD;
        float s0 = 0.0f, s1 = 0.0f;
#pragma unroll
        for (int u = 0; u < 16; ++u) {
            int d = dstart + u;
            float k32 = __bfloat162float(kh[d]) + __bfloat162float(kl[d]);
            float q0 = __bfloat162float(*(const __nv_bfloat16*)(fsm + r0l * 144 + d * 2))
                     + __bfloat162float(*(const __nv_bfloat16*)(fsm + FL_ARR + r0l * 144 + d * 2));
            float q1 = __bfloat162float(*(const __nv_bfloat16*)(fsm + r1l * 144 + d * 2))
                     + __bfloat162float(*(const __nv_bfloat16*)(fsm + FL_ARR + r1l * 144 + d * 2));
            s0 = fmaf(q0, k32, s0);
            s1 = fmaf(q1, k32, s1);
        }
        s0 += __shfl_xor_sync(0xffffffffu, s0, 1);
        s0 += __shfl_xor_sync(0xffffffffu, s0, 2);
        s1 += __shfl_xor_sync(0xffffffffu, s1, 1);
        s1 += __shfl_xor_sync(0xffffffffu, s1, 2);

        float mn0 = fmaxf(m0, s0), mn1 = fmaxf(m1, s1);
        float sc0 = fexp(m0 - mn0), sc1 = fexp(m1 - mn1);
        float p0 = fexp(s0 - mn0),  p1 = fexp(s1 - mn1);
        m0 = mn0; m1 = mn1;
        l0 = l0 * sc0 + p0;
        l1 = l1 * sc1 + p1;

        const __nv_bfloat16* vh = g_vh + head + (size_t)576 * DD;
        const __nv_bfloat16* vl = g_vl + head + (size_t)576 * DD;
#pragma unroll
        for (int nf = 0; nf < 8; ++nf) {
            int d = nf * 8 + d0;
            float va = __bfloat162float(vh[d])     + __bfloat162float(vl[d]);
            float vb = __bfloat162float(vh[d + 1]) + __bfloat162float(vl[d + 1]);
            oacc[nf][0] = oacc[nf][0] * sc0 + p0 * va;
            oacc[nf][1] = oacc[nf][1] * sc0 + p0 * vb;
            oacc[nf][2] = oacc[nf][2] * sc1 + p1 * va;
            oacc[nf][3] = oacc[nf][3] * sc1 + p1 * vb;
        }
    }

    // ---- normalize + bf16 hi/lo write to [B,N,H*D] ----
    const float inv0 = 1.0f / l0, inv1 = 1.0f / l1;
    const int qr0 = qbase + wid * 16 + (lane >> 2);
    const int d0 = (lane & 3) * 2;
    if (qr0 < NT) {
        size_t o = ((size_t)b * NT + qr0) * CC + h * DD;
#pragma unroll
        for (int nf = 0; nf < 8; ++nf) {
            uint32_t hi, lo;
            split2(oacc[nf][0] * inv0, oacc[nf][1] * inv0, hi, lo);
            *(uint32_t*)(g_ohi + o + nf * 8 + d0) = hi;
            *(uint32_t*)(g_olo + o + nf * 8 + d0) = lo;
        }
    }
    const int qr1 = qr0 + 8;
    if (qr1 < NT) {
        size_t o = ((size_t)b * NT + qr1) * CC + h * DD;
#pragma unroll
        for (int nf = 0; nf < 8; ++nf) {
            uint32_t hi, lo;
            split2(oacc[nf][2] * inv1, oacc[nf][3] * inv1, hi, lo);
            *(uint32_t*)(g_ohi + o + nf * 8 + d0) = hi;
            *(uint32_t*)(g_olo + o + nf * 8 + d0) = lo;
        }
    }
}

// ---------------------------------------------------------------------------

extern "C" void kernel_launch(void* const* d_in, const int* in_sizes, int n_in,
                              void* d_out, int out_size)
{
    const float* x      = (const float*)d_in[0];
    const float* rope   = (const float*)d_in[1];
    const float* qkv_w  = (const float*)d_in[2];
    const float* q_bias = (const float*)d_in[3];
    const float* v_bias = (const float*)d_in[4];
    const float* proj_w = (const float*)d_in[5];
    const float* proj_b = (const float*)d_in[6];
    float* out = (float*)d_out;
    (void)in_sizes; (void)n_in; (void)out_size;

    // 0) split fp32 inputs/weights into bf16 hi/lo
    const int total4 = (MM * CC + QKV_N * CC + CC * CC) / 4;
    split_kernel<<<(total4 + 255) / 256, 256>>>(x, qkv_w, proj_w);

    const int mtiles = (MM + 127) / 128;   // 145

    // 1) QKV GEMM (R7 128x128 config) -> q/k/v bf16 hi/lo
    cudaFuncSetAttribute(mma_gemm_qkv,
                         cudaFuncAttributeMaxDynamicSharedMemorySize, QDSMEM);
    mma_gemm_qkv<<<dim3(QKV_N / 128, mtiles), 256, QDSMEM>>>(
        q_bias, v_bias, rope);

    // 2) tensor-core flash attention (9 tiles + fp32 tail) -> g_ohi/g_olo
    cudaFuncSetAttribute(flash_mma,
                         cudaFuncAttributeMaxDynamicSharedMemorySize, FL_SMEM);
    flash_mma<<<dim3(10, BB * HH), 128, FL_SMEM>>>();

    // 3) output projection (R10 128x256 config) -> out
    cudaFuncSetAttribute(mma_gemm_proj,
                         cudaFuncAttributeMaxDynamicSharedMemorySize, PDSMEM);
    mma_gemm_proj<<<dim3(CC / 256, mtiles), 256, PDSMEM>>>(proj_b, out);
}